// round 2
// baseline (speedup 1.0000x reference)
#include <cuda_runtime.h>

// FraudDetectionHybrid: the autoencoder branch (enc_*/dec_*) is dead code —
// `recon` is never used in the reference output. Output depends only on the
// fraud tanh stack, the collapsed 2x2 conv, and the 2->4->2 sampler softmax.
//
// Per sample (x0,x1):
//   h = x;  4x: h_i = tanh(W[l] h + b[l])        (2x2 each)
//   conv = sigmoid(h0*(k00+k10) + h1*(k01+k11))  (patch = [[h0,h1],[h0,h1]])
//   t_j  = tanh(s_W1[j,0]*h0 + s_W1[j,1]*conv + s_b1[j]), j=0..3
//   l_i  = sum_j t_j * s_W2[i,j] + s_b2[i]
//   out  = softmax(l)  (2-way)
//
// 4 samples per thread via two float4 loads/stores (x and out are [B,2] f32).

__global__ __launch_bounds__(256, 4)
void fraud_kernel(const float4* __restrict__ x4,
                  const float*  __restrict__ fraud_W,   // [4,2,2]
                  const float*  __restrict__ fraud_b,   // [4,2]
                  const float*  __restrict__ conv_k,    // [2,2]
                  const float*  __restrict__ s_W1,      // [4,2]
                  const float*  __restrict__ s_b1,      // [4]
                  const float*  __restrict__ s_W2,      // [2,4]
                  const float*  __restrict__ s_b2,      // [2]
                  float4* __restrict__ out4,
                  int n_threads)
{
    int t = blockIdx.x * blockDim.x + threadIdx.x;
    if (t >= n_threads) return;

    // ---- uniform weights -> registers (amortized over 4 samples) ----
    float fW[16], fb[8], W1[8], b1[4], W2[8], b2[2];
#pragma unroll
    for (int i = 0; i < 16; i++) fW[i] = __ldg(fraud_W + i);
#pragma unroll
    for (int i = 0; i < 8; i++)  fb[i] = __ldg(fraud_b + i);
#pragma unroll
    for (int i = 0; i < 8; i++)  W1[i] = __ldg(s_W1 + i);
#pragma unroll
    for (int i = 0; i < 4; i++)  b1[i] = __ldg(s_b1 + i);
#pragma unroll
    for (int i = 0; i < 8; i++)  W2[i] = __ldg(s_W2 + i);
#pragma unroll
    for (int i = 0; i < 2; i++)  b2[i] = __ldg(s_b2 + i);
    const float c0 = __ldg(conv_k + 0) + __ldg(conv_k + 2);
    const float c1 = __ldg(conv_k + 1) + __ldg(conv_k + 3);

    // ---- load 4 samples ----
    float4 in0 = x4[2 * t + 0];
    float4 in1 = x4[2 * t + 1];
    float hx[4] = { in0.x, in0.z, in1.x, in1.z };
    float hy[4] = { in0.y, in0.w, in1.y, in1.w };

    float p0[4], p1[4];
#pragma unroll
    for (int s = 0; s < 4; s++) {
        float h0 = hx[s], h1 = hy[s];
        // fraud net: 4 stacked 2x2 affine + tanh
#pragma unroll
        for (int l = 0; l < 4; l++) {
            float z0 = fmaf(fW[l * 4 + 0], h0, fmaf(fW[l * 4 + 1], h1, fb[l * 2 + 0]));
            float z1 = fmaf(fW[l * 4 + 2], h0, fmaf(fW[l * 4 + 3], h1, fb[l * 2 + 1]));
            h0 = tanhf(z0);
            h1 = tanhf(z1);
        }
        // collapsed 2x2 "quantum" conv + sigmoid (CONV_THRESHOLD = 0)
        float zc = fmaf(c0, h0, c1 * h1);
        float conv = 1.0f / (1.0f + expf(-zc));
        // sampler QNN: 2 -> 4 (tanh) -> 2
        float tt[4];
#pragma unroll
        for (int j = 0; j < 4; j++)
            tt[j] = tanhf(fmaf(W1[2 * j], h0, fmaf(W1[2 * j + 1], conv, b1[j])));
        float l0 = fmaf(tt[3], W2[3], fmaf(tt[2], W2[2], fmaf(tt[1], W2[1], fmaf(tt[0], W2[0], b2[0]))));
        float l1 = fmaf(tt[3], W2[7], fmaf(tt[2], W2[6], fmaf(tt[1], W2[5], fmaf(tt[0], W2[4], b2[1]))));
        // 2-way stable softmax
        float m  = fmaxf(l0, l1);
        float e0 = expf(l0 - m);
        float e1 = expf(l1 - m);
        float inv = 1.0f / (e0 + e1);
        p0[s] = e0 * inv;
        p1[s] = e1 * inv;
    }

    out4[2 * t + 0] = make_float4(p0[0], p1[0], p0[1], p1[1]);
    out4[2 * t + 1] = make_float4(p0[2], p1[2], p0[3], p1[3]);
}

extern "C" void kernel_launch(void* const* d_in, const int* in_sizes, int n_in,
                              void* d_out, int out_size)
{
    const int B = in_sizes[0] / 2;          // x is [B,2] float32
    const int n_threads = B / 4;            // 4 samples per thread (B = 1<<20, divisible)
    const int block = 256;
    const int grid = (n_threads + block - 1) / block;

    fraud_kernel<<<grid, block>>>(
        (const float4*)d_in[0],             // x
        (const float*)d_in[1],              // fraud_W
        (const float*)d_in[2],              // fraud_b
        (const float*)d_in[15],             // conv_k
        (const float*)d_in[16],             // s_W1
        (const float*)d_in[17],             // s_b1
        (const float*)d_in[18],             // s_W2
        (const float*)d_in[19],             // s_b2
        (float4*)d_out,
        n_threads);
}

// round 3
// speedup vs baseline: 1.5598x; 1.5598x over previous
#include <cuda_runtime.h>

// FraudDetectionHybrid — autoencoder branch is dead code (recon unused).
// R2: replace software tanhf/expf (~25 instr each) with HW MUFU:
//   - tanh.approx.f32  (1 instr, abs err ~5e-4; budget is 1e-3 with 9e-8 baseline)
//   - __expf           (ex2.approx-based, rel err ~1e-6)
//   - 2-way softmax collapsed to a single sigmoid of the logit difference.

__device__ __forceinline__ float tanh_fast(float x) {
    float y;
    asm("tanh.approx.f32 %0, %1;" : "=f"(y) : "f"(x));
    return y;
}

__global__ __launch_bounds__(256, 4)
void fraud_kernel(const float4* __restrict__ x4,
                  const float*  __restrict__ fraud_W,   // [4,2,2]
                  const float*  __restrict__ fraud_b,   // [4,2]
                  const float*  __restrict__ conv_k,    // [2,2]
                  const float*  __restrict__ s_W1,      // [4,2]
                  const float*  __restrict__ s_b1,      // [4]
                  const float*  __restrict__ s_W2,      // [2,4]
                  const float*  __restrict__ s_b2,      // [2]
                  float4* __restrict__ out4,
                  int n_threads)
{
    int t = blockIdx.x * blockDim.x + threadIdx.x;
    if (t >= n_threads) return;

    // ---- uniform weights -> registers ----
    float fW[16], fb[8], W1[8], b1[4], W2[8], b2[2];
#pragma unroll
    for (int i = 0; i < 16; i++) fW[i] = __ldg(fraud_W + i);
#pragma unroll
    for (int i = 0; i < 8; i++)  fb[i] = __ldg(fraud_b + i);
#pragma unroll
    for (int i = 0; i < 8; i++)  W1[i] = __ldg(s_W1 + i);
#pragma unroll
    for (int i = 0; i < 4; i++)  b1[i] = __ldg(s_b1 + i);
#pragma unroll
    for (int i = 0; i < 8; i++)  W2[i] = __ldg(s_W2 + i);
#pragma unroll
    for (int i = 0; i < 2; i++)  b2[i] = __ldg(s_b2 + i);
    const float c0 = __ldg(conv_k + 0) + __ldg(conv_k + 2);
    const float c1 = __ldg(conv_k + 1) + __ldg(conv_k + 3);
    // precompute logit-difference weights: d_j = W2[1,j] - W2[0,j]
    const float dW0 = W2[4] - W2[0];
    const float dW1 = W2[5] - W2[1];
    const float dW2 = W2[6] - W2[2];
    const float dW3 = W2[7] - W2[3];
    const float db  = b2[1] - b2[0];

    // ---- load 4 samples ----
    float4 in0 = x4[2 * t + 0];
    float4 in1 = x4[2 * t + 1];
    float hx[4] = { in0.x, in0.z, in1.x, in1.z };
    float hy[4] = { in0.y, in0.w, in1.y, in1.w };

    float p0[4], p1[4];
#pragma unroll
    for (int s = 0; s < 4; s++) {
        float h0 = hx[s], h1 = hy[s];
        // fraud net: 4 stacked 2x2 affine + tanh (HW MUFU)
#pragma unroll
        for (int l = 0; l < 4; l++) {
            float z0 = fmaf(fW[l * 4 + 0], h0, fmaf(fW[l * 4 + 1], h1, fb[l * 2 + 0]));
            float z1 = fmaf(fW[l * 4 + 2], h0, fmaf(fW[l * 4 + 3], h1, fb[l * 2 + 1]));
            h0 = tanh_fast(z0);
            h1 = tanh_fast(z1);
        }
        // collapsed 2x2 conv + sigmoid
        float zc   = fmaf(c0, h0, c1 * h1);
        float conv = __fdividef(1.0f, 1.0f + __expf(-zc));
        // sampler: 2 -> 4 (tanh)
        float tt[4];
#pragma unroll
        for (int j = 0; j < 4; j++)
            tt[j] = tanh_fast(fmaf(W1[2 * j], h0, fmaf(W1[2 * j + 1], conv, b1[j])));
        // softmax over 2 logits == sigmoid of logit difference
        float dl = fmaf(tt[3], dW3, fmaf(tt[2], dW2, fmaf(tt[1], dW1, fmaf(tt[0], dW0, db))));
        float q  = __fdividef(1.0f, 1.0f + __expf(dl));   // p0 = 1/(1+e^(l1-l0))
        p0[s] = q;
        p1[s] = 1.0f - q;
    }

    out4[2 * t + 0] = make_float4(p0[0], p1[0], p0[1], p1[1]);
    out4[2 * t + 1] = make_float4(p0[2], p1[2], p0[3], p1[3]);
}

extern "C" void kernel_launch(void* const* d_in, const int* in_sizes, int n_in,
                              void* d_out, int out_size)
{
    const int B = in_sizes[0] / 2;          // x is [B,2] float32
    const int n_threads = B / 4;            // 4 samples per thread
    const int block = 256;
    const int grid = (n_threads + block - 1) / block;

    fraud_kernel<<<grid, block>>>(
        (const float4*)d_in[0],             // x
        (const float*)d_in[1],              // fraud_W
        (const float*)d_in[2],              // fraud_b
        (const float*)d_in[15],             // conv_k
        (const float*)d_in[16],             // s_W1
        (const float*)d_in[17],             // s_b1
        (const float*)d_in[18],             // s_W2
        (const float*)d_in[19],             // s_b2
        (float4*)d_out,
        n_threads);
}